// round 6
// baseline (speedup 1.0000x reference)
#include <cuda_runtime.h>
#include <cuda_fp16.h>
#include <cstdint>

#define dE 8
#define dH 1024
#define dI 4096
#define dN 2048
#define dK 2
#define dNK 4096

#define TBM 128
#define TBN 64
#define TBK 16
#define NTH 256

// smem half2-word layout: row stride 9 words (8 + 1 pad, odd => conflict-free)
#define AST 9
#define A_WORDS (128 * AST)           // 1152 per stage
#define B_WORDS (64 * AST)            // 576 per stage
#define SA(s, r, c)  ((s) * A_WORDS + (r) * AST + (c))
#define SB1(s, n, c) (2 * A_WORDS + (s) * B_WORDS + (n) * AST + (c))
#define SB3(s, n, c) (2 * A_WORDS + 2 * B_WORDS + (s) * B_WORDS + (n) * AST + (c))

// ---- scratch (device globals; no runtime allocation) ----
__device__ int    g_pairs[dNK];
__device__ int    g_off[dE + 1];
__device__ __half g_h[(size_t)dNK * dI];   // SwiGLU hidden, fp16 (32 MB)
__device__ float  g_y[(size_t)dNK * dH];   // per-pair weighted output (16 MB)

__device__ __forceinline__ uint32_t packh2(float lo, float hi) {
    __half2 h = __floats2half2_rn(lo, hi);   // .x = lo (low 16 bits)
    return *(uint32_t*)&h;
}
__device__ __forceinline__ void mma_f16(float* d, const uint32_t* a, const uint32_t* b) {
    asm volatile("mma.sync.aligned.m16n8k16.row.col.f32.f16.f16.f32 "
                 "{%0,%1,%2,%3}, {%4,%5,%6,%7}, {%8,%9}, {%0,%1,%2,%3};\n"
                 : "+f"(d[0]), "+f"(d[1]), "+f"(d[2]), "+f"(d[3])
                 : "r"(a[0]), "r"(a[1]), "r"(a[2]), "r"(a[3]),
                   "r"(b[0]), "r"(b[1]));
}

// ---- routing: histogram + scan + scatter, single CTA ----
__global__ void route_kernel(const int* __restrict__ idx) {
    __shared__ int s_cnt[dE], s_base[dE];
    int t = threadIdx.x;
    if (t < dE) s_cnt[t] = 0;
    __syncthreads();
    for (int p = t; p < dNK; p += blockDim.x) atomicAdd(&s_cnt[idx[p]], 1);
    __syncthreads();
    if (t == 0) {
        int acc = 0;
        for (int e = 0; e < dE; ++e) { g_off[e] = acc; s_base[e] = acc; acc += s_cnt[e]; }
        g_off[dE] = acc;
    }
    __syncthreads();
    if (t < dE) s_cnt[t] = 0;
    __syncthreads();
    for (int p = t; p < dNK; p += blockDim.x) {
        int e = idx[p];
        int slot = s_base[e] + atomicAdd(&s_cnt[e], 1);
        g_pairs[slot] = p;
    }
}

// ============ GEMM1 (fp16 mma): h = silu(x@w1) * (x@w3) ============
// CTA 128x64, 8 warps (4m x 2n), warp tile 32x32
// grid: x = M-slot (fastest -> same-B CTAs concurrent), y = N-tile, z = expert
__global__ void __launch_bounds__(NTH, 2)
gemm1_mma(const float* __restrict__ x,
          const float* __restrict__ w1,
          const float* __restrict__ w3) {
    const int e    = blockIdx.z;
    const int mEnd = g_off[e + 1];
    const int m0   = g_off[e] + blockIdx.x * TBM;
    if (m0 >= mEnd) return;
    const int i0 = blockIdx.y * TBN;

    __shared__ uint32_t dsm[2 * A_WORDS + 4 * B_WORDS];   // 18 KB
    __shared__ int s_tok[TBM];

    const int t = threadIdx.x;
    const int w = t >> 5, l = t & 31;
    const int wm = w & 3, wn = w >> 2;
    const int lr = l >> 2, lc = l & 3;

    if (t < TBM) { int s = m0 + t; s_tok[t] = (s < mEnd) ? g_pairs[s] / dK : -1; }
    __syncthreads();

    const float* w1e = w1 + (size_t)e * dH * dI + i0;
    const float* w3e = w3 + (size_t)e * dH * dI + i0;

    // staging coords
    const int aR = t >> 2, aK = (t & 3) * 4;       // A: rows aR, aR+64; 4 k's
    const int bK = (t >> 5) * 2, bN0 = t & 31;     // B: k pair, n = bN0 + 32j

    float4 rA[2];
    float  rB1[2][2], rB3[2][2];

    auto ldg_stage = [&](int kt) {
        const int k0 = kt * TBK;
        #pragma unroll
        for (int j = 0; j < 2; ++j) {
            int tok = s_tok[aR + j * 64];
            rA[j] = *(const float4*)(x + (size_t)(tok < 0 ? 0 : tok) * dH + k0 + aK);
        }
        #pragma unroll
        for (int j = 0; j < 2; ++j) {
            int n = bN0 + 32 * j;
            const float* p1 = w1e + (size_t)(k0 + bK) * dI + n;
            const float* p3 = w3e + (size_t)(k0 + bK) * dI + n;
            rB1[j][0] = p1[0];  rB1[j][1] = p1[dI];
            rB3[j][0] = p3[0];  rB3[j][1] = p3[dI];
        }
    };
    auto sts_stage = [&](int s) {
        #pragma unroll
        for (int j = 0; j < 2; ++j) {
            uint32_t w0 = packh2(rA[j].x, rA[j].y);
            uint32_t w1_ = packh2(rA[j].z, rA[j].w);
            uint32_t* p = &dsm[SA(s, aR + j * 64, aK >> 1)];
            p[0] = w0; p[1] = w1_;
        }
        #pragma unroll
        for (int j = 0; j < 2; ++j) {
            int n = bN0 + 32 * j;
            dsm[SB1(s, n, bK >> 1)] = packh2(rB1[j][0], rB1[j][1]);
            dsm[SB3(s, n, bK >> 1)] = packh2(rB3[j][0], rB3[j][1]);
        }
    };

    float accG[2][4][4] = {};
    float accU[2][4][4] = {};

    const int KT = dH / TBK;   // 64
    ldg_stage(0);
    sts_stage(0);
    __syncthreads();

    for (int kt = 0; kt < KT; ++kt) {
        const int s = kt & 1;
        if (kt + 1 < KT) ldg_stage(kt + 1);

        uint32_t af[2][4];
        #pragma unroll
        for (int mi = 0; mi < 2; ++mi) {
            int r = wm * 32 + mi * 16 + lr;
            af[mi][0] = dsm[SA(s, r,     lc)];
            af[mi][1] = dsm[SA(s, r + 8, lc)];
            af[mi][2] = dsm[SA(s, r,     lc + 4)];
            af[mi][3] = dsm[SA(s, r + 8, lc + 4)];
        }
        #pragma unroll
        for (int ni = 0; ni < 4; ++ni) {
            int col = wn * 32 + ni * 8 + lr;
            uint32_t b1f[2], b3f[2];
            b1f[0] = dsm[SB1(s, col, lc)];
            b1f[1] = dsm[SB1(s, col, lc + 4)];
            b3f[0] = dsm[SB3(s, col, lc)];
            b3f[1] = dsm[SB3(s, col, lc + 4)];
            #pragma unroll
            for (int mi = 0; mi < 2; ++mi) {
                mma_f16(accG[mi][ni], af[mi], b1f);
                mma_f16(accU[mi][ni], af[mi], b3f);
            }
        }

        if (kt + 1 < KT) sts_stage(s ^ 1);
        __syncthreads();
    }

    #pragma unroll
    for (int mi = 0; mi < 2; ++mi) {
        int r0 = m0 + wm * 32 + mi * 16 + lr;
        int r1 = r0 + 8;
        #pragma unroll
        for (int ni = 0; ni < 4; ++ni) {
            int c = i0 + wn * 32 + ni * 8 + lc * 2;
            if (r0 < mEnd) {
                float g0 = accG[mi][ni][0], g1 = accG[mi][ni][1];
                float u0 = accU[mi][ni][0], u1 = accU[mi][ni][1];
                float h0 = g0 / (1.0f + __expf(-g0)) * u0;
                float h1 = g1 / (1.0f + __expf(-g1)) * u1;
                *(uint32_t*)&g_h[(size_t)r0 * dI + c] = packh2(h0, h1);
            }
            if (r1 < mEnd) {
                float g2 = accG[mi][ni][2], g3 = accG[mi][ni][3];
                float u2 = accU[mi][ni][2], u3 = accU[mi][ni][3];
                float h2 = g2 / (1.0f + __expf(-g2)) * u2;
                float h3 = g3 / (1.0f + __expf(-g3)) * u3;
                *(uint32_t*)&g_h[(size_t)r1 * dI + c] = packh2(h2, h3);
            }
        }
    }
}

// ============ GEMM2 (fp16 mma): y = ew * (h @ w2) ============
// grid: x = M-slot, y = N-tile, z = expert
__global__ void __launch_bounds__(NTH, 2)
gemm2_mma(const float* __restrict__ ew,
          const float* __restrict__ w2) {
    const int e    = blockIdx.z;
    const int mEnd = g_off[e + 1];
    const int m0   = g_off[e] + blockIdx.x * TBM;
    if (m0 >= mEnd) return;
    const int h0 = blockIdx.y * TBN;

    __shared__ uint32_t dsm[2 * A_WORDS + 2 * B_WORDS];   // 13.5 KB

    const int t = threadIdx.x;
    const int w = t >> 5, l = t & 31;
    const int wm = w & 3, wn = w >> 2;
    const int lr = l >> 2, lc = l & 3;

    const float* w2e = w2 + (size_t)e * dI * dH + h0;

    const int aR = t >> 2, aK = (t & 3) * 4;
    const int bK = (t >> 5) * 2, bN0 = t & 31;

    uint2 rA[2];                       // 4 halfs (4 k's), already packed pairs
    float rB[2][2];

    auto ldg_stage = [&](int kt) {
        const int k0 = kt * TBK;
        #pragma unroll
        for (int j = 0; j < 2; ++j) {
            int r = aR + j * 64;
            int row = (m0 + r < mEnd) ? (m0 + r) : m0;
            rA[j] = *(const uint2*)(g_h + (size_t)row * dI + k0 + aK);
        }
        #pragma unroll
        for (int j = 0; j < 2; ++j) {
            int n = bN0 + 32 * j;
            const float* p = w2e + (size_t)(k0 + bK) * dH + n;
            rB[j][0] = p[0];  rB[j][1] = p[dH];
        }
    };
    auto sts_stage = [&](int s) {
        #pragma unroll
        for (int j = 0; j < 2; ++j) {
            uint32_t* p = &dsm[SA(s, aR + j * 64, aK >> 1)];
            p[0] = rA[j].x; p[1] = rA[j].y;
        }
        #pragma unroll
        for (int j = 0; j < 2; ++j) {
            int n = bN0 + 32 * j;
            dsm[SB1(s, n, bK >> 1)] = packh2(rB[j][0], rB[j][1]);
        }
    };

    float acc[2][4][4] = {};

    const int KT = dI / TBK;   // 256
    ldg_stage(0);
    sts_stage(0);
    __syncthreads();

    for (int kt = 0; kt < KT; ++kt) {
        const int s = kt & 1;
        if (kt + 1 < KT) ldg_stage(kt + 1);

        uint32_t af[2][4];
        #pragma unroll
        for (int mi = 0; mi < 2; ++mi) {
            int r = wm * 32 + mi * 16 + lr;
            af[mi][0] = dsm[SA(s, r,     lc)];
            af[mi][1] = dsm[SA(s, r + 8, lc)];
            af[mi][2] = dsm[SA(s, r,     lc + 4)];
            af[mi][3] = dsm[SA(s, r + 8, lc + 4)];
        }
        #pragma unroll
        for (int ni = 0; ni < 4; ++ni) {
            int col = wn * 32 + ni * 8 + lr;
            uint32_t bf[2];
            bf[0] = dsm[SB1(s, col, lc)];
            bf[1] = dsm[SB1(s, col, lc + 4)];
            #pragma unroll
            for (int mi = 0; mi < 2; ++mi)
                mma_f16(acc[mi][ni], af[mi], bf);
        }

        if (kt + 1 < KT) sts_stage(s ^ 1);
        __syncthreads();
    }

    #pragma unroll
    for (int mi = 0; mi < 2; ++mi) {
        int r0 = m0 + wm * 32 + mi * 16 + lr;
        int r1 = r0 + 8;
        int p0 = -1, p1 = -1;
        float wg0 = 0.0f, wg1 = 0.0f;
        if (r0 < mEnd) { p0 = g_pairs[r0]; wg0 = ew[p0]; }
        if (r1 < mEnd) { p1 = g_pairs[r1]; wg1 = ew[p1]; }
        #pragma unroll
        for (int ni = 0; ni < 4; ++ni) {
            int c = h0 + wn * 32 + ni * 8 + lc * 2;
            if (p0 >= 0) {
                float2 v = { wg0 * acc[mi][ni][0], wg0 * acc[mi][ni][1] };
                *(float2*)&g_y[(size_t)p0 * dH + c] = v;
            }
            if (p1 >= 0) {
                float2 v = { wg1 * acc[mi][ni][2], wg1 * acc[mi][ni][3] };
                *(float2*)&g_y[(size_t)p1 * dH + c] = v;
            }
        }
    }
}

// ---- final reduce over top-k: out[n] = y[2n] + y[2n+1] ----
__global__ void reduce_kernel(float* __restrict__ out) {
    int i = blockIdx.x * blockDim.x + threadIdx.x;
    if (i >= dN * dH / 4) return;
    int n  = i / (dH / 4);
    int hg = i % (dH / 4);
    const float4* y0 = (const float4*)&g_y[(size_t)(2 * n) * dH];
    const float4* y1 = (const float4*)&g_y[(size_t)(2 * n + 1) * dH];
    float4 a = y0[hg], b = y1[hg];
    float4 r = { a.x + b.x, a.y + b.y, a.z + b.z, a.w + b.w };
    ((float4*)out)[i] = r;
}

extern "C" void kernel_launch(void* const* d_in, const int* in_sizes, int n_in,
                              void* d_out, int out_size) {
    const float* x   = (const float*)d_in[0];
    const int*   idx = (const int*)  d_in[1];
    const float* ew  = (const float*)d_in[2];
    const float* w1  = (const float*)d_in[3];
    const float* w2  = (const float*)d_in[4];
    const float* w3  = (const float*)d_in[5];
    float* out = (float*)d_out;

    route_kernel<<<1, 256>>>(idx);
    dim3 g1(dNK / TBM, dI / TBN, dE);   // x = M-slots (32, mostly empty), y = 64 N-tiles
    gemm1_mma<<<g1, NTH>>>(x, w1, w3);
    dim3 g2(dNK / TBM, dH / TBN, dE);   // x = M-slots, y = 16 N-tiles
    gemm2_mma<<<g2, NTH>>>(ew, w2);
    reduce_kernel<<<(dN * dH / 4 + 255) / 256, 256>>>(out);
}

// round 8
// speedup vs baseline: 1.0833x; 1.0833x over previous
#include <cuda_runtime.h>
#include <cuda_fp16.h>
#include <cstdint>

#define dE 8
#define dH 1024
#define dI 4096
#define dN 2048
#define dK 2
#define dNK 4096

#define TBM 128
#define TBN 64
#define TBK 16
#define NTH 256

// smem half2-word layout: row stride 12 words (48B) — 16B-aligned rows for
// ldmatrix, and 12r mod 32 cycles through distinct bank quads (conflict-free)
#define AST 12
#define A_WORDS (128 * AST)           // 1536 per stage
#define B_WORDS (64 * AST)            // 768 per stage
#define SA(s, r, c)  ((s) * A_WORDS + (r) * AST + (c))
#define SB1(s, n, c) (2 * A_WORDS + (s) * B_WORDS + (n) * AST + (c))
#define SB3(s, n, c) (2 * A_WORDS + 2 * B_WORDS + (s) * B_WORDS + (n) * AST + (c))

// ---- scratch (device globals; no runtime allocation) ----
__device__ int    g_pairs[dNK];
__device__ int    g_off[dE + 1];
__device__ __half g_h[(size_t)dNK * dI];   // SwiGLU hidden, fp16 (32 MB)
__device__ float  g_y[(size_t)dNK * dH];   // per-pair weighted output (16 MB)

__device__ __forceinline__ uint32_t su32(const void* p) {
    return (uint32_t)__cvta_generic_to_shared(p);
}
__device__ __forceinline__ uint32_t packh2(float lo, float hi) {
    __half2 h = __floats2half2_rn(lo, hi);   // .x = lo (low 16 bits)
    return *(uint32_t*)&h;
}
__device__ __forceinline__ void mma_f16(float* d, const uint32_t* a, const uint32_t* b) {
    asm volatile("mma.sync.aligned.m16n8k16.row.col.f32.f16.f16.f32 "
                 "{%0,%1,%2,%3}, {%4,%5,%6,%7}, {%8,%9}, {%0,%1,%2,%3};\n"
                 : "+f"(d[0]), "+f"(d[1]), "+f"(d[2]), "+f"(d[3])
                 : "r"(a[0]), "r"(a[1]), "r"(a[2]), "r"(a[3]),
                   "r"(b[0]), "r"(b[1]));
}
__device__ __forceinline__ void ldmx4(uint32_t* r, uint32_t addr) {
    asm volatile("ldmatrix.sync.aligned.m8n8.x4.shared.b16 {%0,%1,%2,%3}, [%4];"
                 : "=r"(r[0]), "=r"(r[1]), "=r"(r[2]), "=r"(r[3]) : "r"(addr));
}

// ---- routing: histogram + scan + scatter, single CTA ----
__global__ void route_kernel(const int* __restrict__ idx) {
    __shared__ int s_cnt[dE], s_base[dE];
    int t = threadIdx.x;
    if (t < dE) s_cnt[t] = 0;
    __syncthreads();
    for (int p = t; p < dNK; p += blockDim.x) atomicAdd(&s_cnt[idx[p]], 1);
    __syncthreads();
    if (t == 0) {
        int acc = 0;
        for (int e = 0; e < dE; ++e) { g_off[e] = acc; s_base[e] = acc; acc += s_cnt[e]; }
        g_off[dE] = acc;
    }
    __syncthreads();
    if (t < dE) s_cnt[t] = 0;
    __syncthreads();
    for (int p = t; p < dNK; p += blockDim.x) {
        int e = idx[p];
        int slot = s_base[e] + atomicAdd(&s_cnt[e], 1);
        g_pairs[slot] = p;
    }
}

// ============ GEMM1 (fp16 mma + ldmatrix): h = silu(x@w1) * (x@w3) ============
// CTA 128x64, 8 warps (4m x 2n), warp tile 32x32
__global__ void __launch_bounds__(NTH, 2)
gemm1_mma(const float* __restrict__ x,
          const float* __restrict__ w1,
          const float* __restrict__ w3) {
    const int e    = blockIdx.z;
    const int mEnd = g_off[e + 1];
    const int m0   = g_off[e] + blockIdx.x * TBM;
    if (m0 >= mEnd) return;
    const int i0 = blockIdx.y * TBN;

    __shared__ __align__(16) uint32_t dsm[2 * A_WORDS + 4 * B_WORDS];   // 24 KB
    __shared__ int s_tok[TBM];

    const int t = threadIdx.x;
    const int w = t >> 5, l = t & 31;
    const int wm = w & 3, wn = w >> 2;
    const int lr = l >> 2, lc = l & 3;
    const uint32_t smb = su32(dsm);

    // ldmatrix lane coords: lanes 0-15 -> rows 0-15 chunk0; 16-31 -> rows 0-15 chunk+4
    const int lmRow = l & 15;
    const int lmChk = (l >> 4) * 4;

    if (t < TBM) { int s = m0 + t; s_tok[t] = (s < mEnd) ? g_pairs[s] / dK : -1; }
    __syncthreads();

    const float* w1e = w1 + (size_t)e * dH * dI + i0;
    const float* w3e = w3 + (size_t)e * dH * dI + i0;

    // staging coords
    const int aR = t >> 2, aK = (t & 3) * 4;       // A: rows aR, aR+64; 4 k's
    const int bK = (t >> 5) * 2, bN0 = t & 31;     // B: k pair, n = bN0 + 32j

    float4 rA[2];
    float  rB1[2][2], rB3[2][2];

    auto ldg_stage = [&](int kt) {
        const int k0 = kt * TBK;
        #pragma unroll
        for (int j = 0; j < 2; ++j) {
            int tok = s_tok[aR + j * 64];
            rA[j] = *(const float4*)(x + (size_t)(tok < 0 ? 0 : tok) * dH + k0 + aK);
        }
        #pragma unroll
        for (int j = 0; j < 2; ++j) {
            int n = bN0 + 32 * j;
            const float* p1 = w1e + (size_t)(k0 + bK) * dI + n;
            const float* p3 = w3e + (size_t)(k0 + bK) * dI + n;
            rB1[j][0] = p1[0];  rB1[j][1] = p1[dI];
            rB3[j][0] = p3[0];  rB3[j][1] = p3[dI];
        }
    };
    auto sts_stage = [&](int s) {
        #pragma unroll
        for (int j = 0; j < 2; ++j) {
            uint32_t w0 = packh2(rA[j].x, rA[j].y);
            uint32_t w1_ = packh2(rA[j].z, rA[j].w);
            uint32_t* p = &dsm[SA(s, aR + j * 64, aK >> 1)];
            p[0] = w0; p[1] = w1_;
        }
        #pragma unroll
        for (int j = 0; j < 2; ++j) {
            int n = bN0 + 32 * j;
            dsm[SB1(s, n, bK >> 1)] = packh2(rB1[j][0], rB1[j][1]);
            dsm[SB3(s, n, bK >> 1)] = packh2(rB3[j][0], rB3[j][1]);
        }
    };

    float accG[2][4][4] = {};
    float accU[2][4][4] = {};

    const int KT = dH / TBK;   // 64
    ldg_stage(0);
    sts_stage(0);
    __syncthreads();

    for (int kt = 0; kt < KT; ++kt) {
        const int s = kt & 1;
        if (kt + 1 < KT) ldg_stage(kt + 1);

        uint32_t af[2][4];
        #pragma unroll
        for (int mi = 0; mi < 2; ++mi) {
            int r = wm * 32 + mi * 16 + lmRow;
            ldmx4(af[mi], smb + 4u * SA(s, r, lmChk));
        }
        // B via ldmatrix.x4: regs = {b[np0][k0], b[np1][k0], b[np0][k8], b[np1][k8]}
        uint32_t b1f[4][2], b3f[4][2];
        #pragma unroll
        for (int np = 0; np < 2; ++np) {
            int n = wn * 32 + np * 16 + lmRow;
            uint32_t q[4];
            ldmx4(q, smb + 4u * SB1(s, n, lmChk));
            b1f[np * 2][0] = q[0]; b1f[np * 2 + 1][0] = q[1];
            b1f[np * 2][1] = q[2]; b1f[np * 2 + 1][1] = q[3];
            ldmx4(q, smb + 4u * SB3(s, n, lmChk));
            b3f[np * 2][0] = q[0]; b3f[np * 2 + 1][0] = q[1];
            b3f[np * 2][1] = q[2]; b3f[np * 2 + 1][1] = q[3];
        }
        #pragma unroll
        for (int ni = 0; ni < 4; ++ni) {
            #pragma unroll
            for (int mi = 0; mi < 2; ++mi) {
                mma_f16(accG[mi][ni], af[mi], b1f[ni]);
                mma_f16(accU[mi][ni], af[mi], b3f[ni]);
            }
        }

        if (kt + 1 < KT) sts_stage(s ^ 1);
        __syncthreads();
    }

    #pragma unroll
    for (int mi = 0; mi < 2; ++mi) {
        int r0 = m0 + wm * 32 + mi * 16 + lr;
        int r1 = r0 + 8;
        #pragma unroll
        for (int ni = 0; ni < 4; ++ni) {
            int c = i0 + wn * 32 + ni * 8 + lc * 2;
            if (r0 < mEnd) {
                float g0 = accG[mi][ni][0], g1 = accG[mi][ni][1];
                float u0 = accU[mi][ni][0], u1 = accU[mi][ni][1];
                float h0 = g0 / (1.0f + __expf(-g0)) * u0;
                float h1 = g1 / (1.0f + __expf(-g1)) * u1;
                *(uint32_t*)&g_h[(size_t)r0 * dI + c] = packh2(h0, h1);
            }
            if (r1 < mEnd) {
                float g2 = accG[mi][ni][2], g3 = accG[mi][ni][3];
                float u2 = accU[mi][ni][2], u3 = accU[mi][ni][3];
                float h2 = g2 / (1.0f + __expf(-g2)) * u2;
                float h3 = g3 / (1.0f + __expf(-g3)) * u3;
                *(uint32_t*)&g_h[(size_t)r1 * dI + c] = packh2(h2, h3);
            }
        }
    }
}

// ============ GEMM2 (fp16 mma + ldmatrix): y = ew * (h @ w2) ============
__global__ void __launch_bounds__(NTH, 2)
gemm2_mma(const float* __restrict__ ew,
          const float* __restrict__ w2) {
    const int e    = blockIdx.z;
    const int mEnd = g_off[e + 1];
    const int m0   = g_off[e] + blockIdx.x * TBM;
    if (m0 >= mEnd) return;
    const int h0 = blockIdx.y * TBN;

    __shared__ __align__(16) uint32_t dsm[2 * A_WORDS + 2 * B_WORDS];   // 18 KB

    const int t = threadIdx.x;
    const int w = t >> 5, l = t & 31;
    const int wm = w & 3, wn = w >> 2;
    const int lr = l >> 2, lc = l & 3;
    const uint32_t smb = su32(dsm);

    const int lmRow = l & 15;
    const int lmChk = (l >> 4) * 4;

    const float* w2e = w2 + (size_t)e * dI * dH + h0;

    const int aR = t >> 2, aK = (t & 3) * 4;
    const int bK = (t >> 5) * 2, bN0 = t & 31;

    uint2 rA[2];                       // 4 halfs (4 k's), already packed pairs
    float rB[2][2];

    auto ldg_stage = [&](int kt) {
        const int k0 = kt * TBK;
        #pragma unroll
        for (int j = 0; j < 2; ++j) {
            int r = aR + j * 64;
            int row = (m0 + r < mEnd) ? (m0 + r) : m0;
            rA[j] = *(const uint2*)(g_h + (size_t)row * dI + k0 + aK);
        }
        #pragma unroll
        for (int j = 0; j < 2; ++j) {
            int n = bN0 + 32 * j;
            const float* p = w2e + (size_t)(k0 + bK) * dH + n;
            rB[j][0] = p[0];  rB[j][1] = p[dH];
        }
    };
    auto sts_stage = [&](int s) {
        #pragma unroll
        for (int j = 0; j < 2; ++j) {
            uint32_t* p = &dsm[SA(s, aR + j * 64, aK >> 1)];
            p[0] = rA[j].x; p[1] = rA[j].y;
        }
        #pragma unroll
        for (int j = 0; j < 2; ++j) {
            int n = bN0 + 32 * j;
            dsm[SB1(s, n, bK >> 1)] = packh2(rB[j][0], rB[j][1]);
        }
    };

    float acc[2][4][4] = {};

    const int KT = dI / TBK;   // 256
    ldg_stage(0);
    sts_stage(0);
    __syncthreads();

    for (int kt = 0; kt < KT; ++kt) {
        const int s = kt & 1;
        if (kt + 1 < KT) ldg_stage(kt + 1);

        uint32_t af[2][4];
        #pragma unroll
        for (int mi = 0; mi < 2; ++mi) {
            int r = wm * 32 + mi * 16 + lmRow;
            ldmx4(af[mi], smb + 4u * SA(s, r, lmChk));
        }
        uint32_t bf[4][2];
        #pragma unroll
        for (int np = 0; np < 2; ++np) {
            int n = wn * 32 + np * 16 + lmRow;
            uint32_t q[4];
            ldmx4(q, smb + 4u * SB1(s, n, lmChk));
            bf[np * 2][0] = q[0]; bf[np * 2 + 1][0] = q[1];
            bf[np * 2][1] = q[2]; bf[np * 2 + 1][1] = q[3];
        }
        #pragma unroll
        for (int ni = 0; ni < 4; ++ni)
            #pragma unroll
            for (int mi = 0; mi < 2; ++mi)
                mma_f16(acc[mi][ni], af[mi], bf[ni]);

        if (kt + 1 < KT) sts_stage(s ^ 1);
        __syncthreads();
    }

    #pragma unroll
    for (int mi = 0; mi < 2; ++mi) {
        int r0 = m0 + wm * 32 + mi * 16 + lr;
        int r1 = r0 + 8;
        int p0 = -1, p1 = -1;
        float wg0 = 0.0f, wg1 = 0.0f;
        if (r0 < mEnd) { p0 = g_pairs[r0]; wg0 = ew[p0]; }
        if (r1 < mEnd) { p1 = g_pairs[r1]; wg1 = ew[p1]; }
        #pragma unroll
        for (int ni = 0; ni < 4; ++ni) {
            int c = h0 + wn * 32 + ni * 8 + lc * 2;
            if (p0 >= 0) {
                float2 v = { wg0 * acc[mi][ni][0], wg0 * acc[mi][ni][1] };
                *(float2*)&g_y[(size_t)p0 * dH + c] = v;
            }
            if (p1 >= 0) {
                float2 v = { wg1 * acc[mi][ni][2], wg1 * acc[mi][ni][3] };
                *(float2*)&g_y[(size_t)p1 * dH + c] = v;
            }
        }
    }
}

// ---- final reduce over top-k: out[n] = y[2n] + y[2n+1] ----
__global__ void reduce_kernel(float* __restrict__ out) {
    int i = blockIdx.x * blockDim.x + threadIdx.x;
    if (i >= dN * dH / 4) return;
    int n  = i / (dH / 4);
    int hg = i % (dH / 4);
    const float4* y0 = (const float4*)&g_y[(size_t)(2 * n) * dH];
    const float4* y1 = (const float4*)&g_y[(size_t)(2 * n + 1) * dH];
    float4 a = y0[hg], b = y1[hg];
    float4 r = { a.x + b.x, a.y + b.y, a.z + b.z, a.w + b.w };
    ((float4*)out)[i] = r;
}

extern "C" void kernel_launch(void* const* d_in, const int* in_sizes, int n_in,
                              void* d_out, int out_size) {
    const float* x   = (const float*)d_in[0];
    const int*   idx = (const int*)  d_in[1];
    const float* ew  = (const float*)d_in[2];
    const float* w1  = (const float*)d_in[3];
    const float* w2  = (const float*)d_in[4];
    const float* w3  = (const float*)d_in[5];
    float* out = (float*)d_out;

    route_kernel<<<1, 256>>>(idx);
    dim3 g1(dNK / TBM, dI / TBN, dE);   // x = M-slots (fastest), y = N-tiles
    gemm1_mma<<<g1, NTH>>>(x, w1, w3);
    dim3 g2(dNK / TBM, dH / TBN, dE);
    gemm2_mma<<<g2, NTH>>>(ew, w2);
    reduce_kernel<<<(dN * dH / 4 + 255) / 256, 256>>>(out);
}

// round 9
// speedup vs baseline: 1.4202x; 1.3110x over previous
#include <cuda_runtime.h>
#include <cuda_fp16.h>
#include <cstdint>

#define dE 8
#define dH 1024
#define dI 4096
#define dN 2048
#define dK 2
#define dNK 4096

#define TBM 128
#define TBN 64
#define TBK 32
#define NTH 256

// smem: row stride 20 words (80B) — 16B-aligned rows for ldmatrix,
// 20r mod 32 cycles through 8 distinct bank quads (conflict-free)
#define AST 20
#define A_WORDS (128 * AST)           // 2560 per stage
#define B_WORDS (64 * AST)            // 1280 per stage
#define SA(s, r, c)  ((s) * A_WORDS + (r) * AST + (c))
#define SB1(s, n, c) (2 * A_WORDS + (s) * B_WORDS + (n) * AST + (c))
#define SB3(s, n, c) (2 * A_WORDS + 2 * B_WORDS + (s) * B_WORDS + (n) * AST + (c))

// ---- scratch (device globals; no runtime allocation) ----
__device__ int    g_pairs[dNK];
__device__ int    g_off[dE + 1];
__device__ __half g_h[(size_t)dNK * dI];   // SwiGLU hidden, fp16 (32 MB)

__device__ __forceinline__ uint32_t su32(const void* p) {
    return (uint32_t)__cvta_generic_to_shared(p);
}
__device__ __forceinline__ uint32_t packh2(float lo, float hi) {
    __half2 h = __floats2half2_rn(lo, hi);
    return *(uint32_t*)&h;
}
__device__ __forceinline__ void mma_f16(float* d, const uint32_t* a, const uint32_t* b) {
    asm volatile("mma.sync.aligned.m16n8k16.row.col.f32.f16.f16.f32 "
                 "{%0,%1,%2,%3}, {%4,%5,%6,%7}, {%8,%9}, {%0,%1,%2,%3};\n"
                 : "+f"(d[0]), "+f"(d[1]), "+f"(d[2]), "+f"(d[3])
                 : "r"(a[0]), "r"(a[1]), "r"(a[2]), "r"(a[3]),
                   "r"(b[0]), "r"(b[1]));
}
__device__ __forceinline__ void ldmx4(uint32_t* r, uint32_t addr) {
    asm volatile("ldmatrix.sync.aligned.m8n8.x4.shared.b16 {%0,%1,%2,%3}, [%4];"
                 : "=r"(r[0]), "=r"(r[1]), "=r"(r[2]), "=r"(r[3]) : "r"(addr));
}

// ---- routing: histogram + scan + scatter, single CTA ----
__global__ void route_kernel(const int* __restrict__ idx) {
    __shared__ int s_cnt[dE], s_base[dE];
    int t = threadIdx.x;
    if (t < dE) s_cnt[t] = 0;
    __syncthreads();
    for (int p = t; p < dNK; p += blockDim.x) atomicAdd(&s_cnt[idx[p]], 1);
    __syncthreads();
    if (t == 0) {
        int acc = 0;
        for (int e = 0; e < dE; ++e) { g_off[e] = acc; s_base[e] = acc; acc += s_cnt[e]; }
        g_off[dE] = acc;
    }
    __syncthreads();
    if (t < dE) s_cnt[t] = 0;
    __syncthreads();
    for (int p = t; p < dNK; p += blockDim.x) {
        int e = idx[p];
        int slot = s_base[e] + atomicAdd(&s_cnt[e], 1);
        g_pairs[slot] = p;
    }
}

// ---- zero the output (gemm2 accumulates into it atomically) ----
__global__ void zero_out_kernel(float* __restrict__ out) {
    int i = blockIdx.x * blockDim.x + threadIdx.x;
    if (i < dN * dH / 4) ((float4*)out)[i] = make_float4(0.f, 0.f, 0.f, 0.f);
}

// ============ GEMM1 (fp16 mma + ldmatrix, k32): h = silu(x@w1)*(x@w3) ============
__global__ void __launch_bounds__(NTH, 2)
gemm1_mma(const float* __restrict__ x,
          const float* __restrict__ w1,
          const float* __restrict__ w3) {
    const int e    = blockIdx.z;
    const int mEnd = g_off[e + 1];
    const int m0   = g_off[e] + blockIdx.x * TBM;
    if (m0 >= mEnd) return;
    const int i0 = blockIdx.y * TBN;

    __shared__ __align__(16) uint32_t dsm[2 * A_WORDS + 4 * B_WORDS];   // 40 KB
    __shared__ int s_tok[TBM];

    const int t = threadIdx.x;
    const int w = t >> 5, l = t & 31;
    const int wm = w & 3, wn = w >> 2;
    const int lr = l >> 2, lc = l & 3;
    const uint32_t smb = su32(dsm);
    const int lmRow = l & 15;
    const int lmChk = (l >> 4) * 4;

    if (t < TBM) { int s = m0 + t; s_tok[t] = (s < mEnd) ? g_pairs[s] / dK : -1; }
    __syncthreads();

    const float* w1e = w1 + (size_t)e * dH * dI + i0;
    const float* w3e = w3 + (size_t)e * dH * dI + i0;

    // --- hoisted staging coords ---
    // A: p=0..3: id = t + p*256; row = id>>3 (0..127); ch = id&7 (8 float4 / row)
    int aOffW[4];
    const float* aSrc[4];
    #pragma unroll
    for (int p = 0; p < 4; ++p) {
        int id = t + p * NTH;
        int row = id >> 3, ch = id & 7;
        aOffW[p] = row * AST + ch * 2;
        int tok = s_tok[row];
        aSrc[p] = x + (size_t)(tok < 0 ? 0 : tok) * dH + ch * 4;
    }
    // B: n = t&63, kb = (t>>6)*8 (8 consecutive k per thread)
    const int bN = t & 63, bKb = (t >> 6) * 8;
    const int bOffW = bN * AST + (bKb >> 1);
    const float* b1Src = w1e + (size_t)bKb * dI + bN;
    const float* b3Src = w3e + (size_t)bKb * dI + bN;

    uint32_t uA[4][2], uB1[4], uB3[4];

    auto ldg_stage = [&](int kt) {
        const int k0 = kt * TBK;
        #pragma unroll
        for (int p = 0; p < 4; ++p) {
            float4 v = *(const float4*)(aSrc[p] + k0);
            uA[p][0] = packh2(v.x, v.y);
            uA[p][1] = packh2(v.z, v.w);
        }
        const float* pb1 = b1Src + (size_t)k0 * dI;
        const float* pb3 = b3Src + (size_t)k0 * dI;
        #pragma unroll
        for (int jj = 0; jj < 4; ++jj) {
            float f0 = pb1[(size_t)(2 * jj) * dI];
            float f1 = pb1[(size_t)(2 * jj + 1) * dI];
            uB1[jj] = packh2(f0, f1);
            f0 = pb3[(size_t)(2 * jj) * dI];
            f1 = pb3[(size_t)(2 * jj + 1) * dI];
            uB3[jj] = packh2(f0, f1);
        }
    };
    auto sts_stage = [&](int s) {
        #pragma unroll
        for (int p = 0; p < 4; ++p)
            *(uint2*)&dsm[s * A_WORDS + aOffW[p]] = make_uint2(uA[p][0], uA[p][1]);
        *(uint4*)&dsm[2 * A_WORDS + s * B_WORDS + bOffW] =
            make_uint4(uB1[0], uB1[1], uB1[2], uB1[3]);
        *(uint4*)&dsm[2 * A_WORDS + 2 * B_WORDS + s * B_WORDS + bOffW] =
            make_uint4(uB3[0], uB3[1], uB3[2], uB3[3]);
    };

    float accG[2][4][4] = {};
    float accU[2][4][4] = {};

    const int KT = dH / TBK;   // 32
    ldg_stage(0);
    sts_stage(0);
    __syncthreads();

    for (int kt = 0; kt < KT; ++kt) {
        const int s = kt & 1;
        if (kt + 1 < KT) ldg_stage(kt + 1);

        #pragma unroll
        for (int ks = 0; ks < 2; ++ks) {
            const int kw = ks * 8 + lmChk;
            uint32_t af[2][4];
            #pragma unroll
            for (int mi = 0; mi < 2; ++mi) {
                int r = wm * 32 + mi * 16 + lmRow;
                ldmx4(af[mi], smb + 4u * (uint32_t)(s * A_WORDS + r * AST + kw));
            }
            uint32_t b1f[4][2], b3f[4][2];
            #pragma unroll
            for (int np = 0; np < 2; ++np) {
                int n = wn * 32 + np * 16 + lmRow;
                uint32_t q[4];
                ldmx4(q, smb + 4u * (uint32_t)SB1(s, n, kw));
                b1f[np * 2][0] = q[0]; b1f[np * 2 + 1][0] = q[1];
                b1f[np * 2][1] = q[2]; b1f[np * 2 + 1][1] = q[3];
                ldmx4(q, smb + 4u * (uint32_t)SB3(s, n, kw));
                b3f[np * 2][0] = q[0]; b3f[np * 2 + 1][0] = q[1];
                b3f[np * 2][1] = q[2]; b3f[np * 2 + 1][1] = q[3];
            }
            #pragma unroll
            for (int ni = 0; ni < 4; ++ni) {
                #pragma unroll
                for (int mi = 0; mi < 2; ++mi) {
                    mma_f16(accG[mi][ni], af[mi], b1f[ni]);
                    mma_f16(accU[mi][ni], af[mi], b3f[ni]);
                }
            }
        }

        if (kt + 1 < KT) sts_stage(s ^ 1);
        __syncthreads();
    }

    #pragma unroll
    for (int mi = 0; mi < 2; ++mi) {
        int r0 = m0 + wm * 32 + mi * 16 + lr;
        int r1 = r0 + 8;
        #pragma unroll
        for (int ni = 0; ni < 4; ++ni) {
            int c = i0 + wn * 32 + ni * 8 + lc * 2;
            if (r0 < mEnd) {
                float g0 = accG[mi][ni][0], g1 = accG[mi][ni][1];
                float u0 = accU[mi][ni][0], u1 = accU[mi][ni][1];
                float h0 = g0 / (1.0f + __expf(-g0)) * u0;
                float h1 = g1 / (1.0f + __expf(-g1)) * u1;
                *(uint32_t*)&g_h[(size_t)r0 * dI + c] = packh2(h0, h1);
            }
            if (r1 < mEnd) {
                float g2 = accG[mi][ni][2], g3 = accG[mi][ni][3];
                float u2 = accU[mi][ni][2], u3 = accU[mi][ni][3];
                float h2 = g2 / (1.0f + __expf(-g2)) * u2;
                float h3 = g3 / (1.0f + __expf(-g3)) * u3;
                *(uint32_t*)&g_h[(size_t)r1 * dI + c] = packh2(h2, h3);
            }
        }
    }
}

// ============ GEMM2 (fp16 mma + ldmatrix, k32): out += ew * (h @ w2) ============
__global__ void __launch_bounds__(NTH, 2)
gemm2_mma(const float* __restrict__ ew,
          const float* __restrict__ w2,
          float* __restrict__ out) {
    const int e    = blockIdx.z;
    const int mEnd = g_off[e + 1];
    const int m0   = g_off[e] + blockIdx.x * TBM;
    if (m0 >= mEnd) return;
    const int h0 = blockIdx.y * TBN;

    __shared__ __align__(16) uint32_t dsm[2 * A_WORDS + 2 * B_WORDS];   // 30 KB

    const int t = threadIdx.x;
    const int w = t >> 5, l = t & 31;
    const int wm = w & 3, wn = w >> 2;
    const int lr = l >> 2, lc = l & 3;
    const uint32_t smb = su32(dsm);
    const int lmRow = l & 15;
    const int lmChk = (l >> 4) * 4;

    const float* w2e = w2 + (size_t)e * dI * dH + h0;

    // A: p=0..1: id = t + p*256; row = id>>2 (0..127); qc = id&3 (4 uint4 / row)
    int aOffW[2];
    const __half* aSrc[2];
    #pragma unroll
    for (int p = 0; p < 2; ++p) {
        int id = t + p * NTH;
        int row = id >> 2, qc = id & 3;
        aOffW[p] = row * AST + qc * 4;
        int grow = (m0 + row < mEnd) ? (m0 + row) : m0;
        aSrc[p] = g_h + (size_t)grow * dI + qc * 8;
    }
    const int bN = t & 63, bKb = (t >> 6) * 8;
    const int bOffW = bN * AST + (bKb >> 1);
    const float* bSrc = w2e + (size_t)bKb * dH + bN;

    uint4 uA[2];
    uint32_t uB[4];

    auto ldg_stage = [&](int kt) {
        const int k0 = kt * TBK;
        #pragma unroll
        for (int p = 0; p < 2; ++p)
            uA[p] = *(const uint4*)(aSrc[p] + k0);
        const float* pb = bSrc + (size_t)k0 * dH;
        #pragma unroll
        for (int jj = 0; jj < 4; ++jj) {
            float f0 = pb[(size_t)(2 * jj) * dH];
            float f1 = pb[(size_t)(2 * jj + 1) * dH];
            uB[jj] = packh2(f0, f1);
        }
    };
    auto sts_stage = [&](int s) {
        #pragma unroll
        for (int p = 0; p < 2; ++p)
            *(uint4*)&dsm[s * A_WORDS + aOffW[p]] = uA[p];
        *(uint4*)&dsm[2 * A_WORDS + s * B_WORDS + bOffW] =
            make_uint4(uB[0], uB[1], uB[2], uB[3]);
    };

    float acc[2][4][4] = {};

    const int KT = dI / TBK;   // 128
    ldg_stage(0);
    sts_stage(0);
    __syncthreads();

    for (int kt = 0; kt < KT; ++kt) {
        const int s = kt & 1;
        if (kt + 1 < KT) ldg_stage(kt + 1);

        #pragma unroll
        for (int ks = 0; ks < 2; ++ks) {
            const int kw = ks * 8 + lmChk;
            uint32_t af[2][4];
            #pragma unroll
            for (int mi = 0; mi < 2; ++mi) {
                int r = wm * 32 + mi * 16 + lmRow;
                ldmx4(af[mi], smb + 4u * (uint32_t)(s * A_WORDS + r * AST + kw));
            }
            uint32_t bf[4][2];
            #pragma unroll
            for (int np = 0; np < 2; ++np) {
                int n = wn * 32 + np * 16 + lmRow;
                uint32_t q[4];
                ldmx4(q, smb + 4u * (uint32_t)(2 * A_WORDS + s * B_WORDS + n * AST + kw));
                bf[np * 2][0] = q[0]; bf[np * 2 + 1][0] = q[1];
                bf[np * 2][1] = q[2]; bf[np * 2 + 1][1] = q[3];
            }
            #pragma unroll
            for (int ni = 0; ni < 4; ++ni)
                #pragma unroll
                for (int mi = 0; mi < 2; ++mi)
                    mma_f16(acc[mi][ni], af[mi], bf[ni]);
        }

        if (kt + 1 < KT) sts_stage(s ^ 1);
        __syncthreads();
    }

    // fused epilogue: out[token] += ew * acc  (exactly 2 adds per element)
    #pragma unroll
    for (int mi = 0; mi < 2; ++mi) {
        int r0 = m0 + wm * 32 + mi * 16 + lr;
        int r1 = r0 + 8;
        int tk0 = -1, tk1 = -1;
        float wg0 = 0.0f, wg1 = 0.0f;
        if (r0 < mEnd) { int p = g_pairs[r0]; wg0 = ew[p]; tk0 = p / dK; }
        if (r1 < mEnd) { int p = g_pairs[r1]; wg1 = ew[p]; tk1 = p / dK; }
        #pragma unroll
        for (int ni = 0; ni < 4; ++ni) {
            int c = h0 + wn * 32 + ni * 8 + lc * 2;
            if (tk0 >= 0) {
                atomicAdd(&out[(size_t)tk0 * dH + c],     wg0 * acc[mi][ni][0]);
                atomicAdd(&out[(size_t)tk0 * dH + c + 1], wg0 * acc[mi][ni][1]);
            }
            if (tk1 >= 0) {
                atomicAdd(&out[(size_t)tk1 * dH + c],     wg1 * acc[mi][ni][2]);
                atomicAdd(&out[(size_t)tk1 * dH + c + 1], wg1 * acc[mi][ni][3]);
            }
        }
    }
}

extern "C" void kernel_launch(void* const* d_in, const int* in_sizes, int n_in,
                              void* d_out, int out_size) {
    const float* x   = (const float*)d_in[0];
    const int*   idx = (const int*)  d_in[1];
    const float* ew  = (const float*)d_in[2];
    const float* w1  = (const float*)d_in[3];
    const float* w2  = (const float*)d_in[4];
    const float* w3  = (const float*)d_in[5];
    float* out = (float*)d_out;

    route_kernel<<<1, 256>>>(idx);
    zero_out_kernel<<<(dN * dH / 4 + 255) / 256, 256>>>(out);
    dim3 g1(dNK / TBM, dI / TBN, dE);   // x = M-slots (fastest), y = N-tiles
    gemm1_mma<<<g1, NTH>>>(x, w1, w3);
    dim3 g2(dNK / TBM, dH / TBN, dE);
    gemm2_mma<<<g2, NTH>>>(ew, w2, out);
}